// round 15
// baseline (speedup 1.0000x reference)
#include <cuda_runtime.h>
#include <cuda_fp16.h>
#include <math.h>
#include <stdint.h>

// ---------------------------------------------------------------------------
// Problem constants
//   B=4, SEQ=1024, DIM=1024, HEADS=16, N_EXP=2, SLOTS=512, HID=4096
// Output: [ y : 4*1024*1024 f32 ][ attn : 4*1024*1024*16 f32 ]
// All GEMM/attention operands fp16 (RNE-rounded at producer), fp32 accumulate.
// ---------------------------------------------------------------------------

// arena offsets in FLOAT units (fp16 buffers occupy elem_count/2 float slots)
#define OFF_TMP      0LL           // 64M halves = 32M floats
#define OFF_PROJ     33554432LL    // 4M f32
#define OFF_X1       37748736LL    // 4M f32
#define OFF_LOGITS   41943040LL    // 4M f32
#define OFF_MOE      46137344LL    // 4M f32
#define OFF_RL       50331648LL    // 64K f32
#define OFF_XH       50397184LL    // 4M halves
#define OFF_WQH      52494336LL    // 1M halves
#define OFF_WKVH     53018624LL    // 2M halves
#define OFF_WPH      54067200LL    // 1M halves
#define OFF_PHIH     54591488LL    // 1M halves
#define OFF_WE1H     55115776LL    // 8M halves
#define OFF_WE2H     59310080LL    // 8M halves
#define OFF_QH       63504384LL    // 4M halves
#define OFF_KVH      65601536LL    // 8M halves
#define OFF_ATTOUTH  69795840LL    // 4M halves
#define OFF_X1H      71892992LL    // 4M halves
#define OFF_DISPTH   73990144LL    // 4M halves
#define OFF_COMBH    76087296LL    // 4M halves
#define OFF_SLOTSH   78184448LL    // 4M halves (4 batches x 1024x1024)
#define OFF_HH       80281600LL    // 16M halves (8 batches x 512x4096)
#define OFF_YMOEH    88670208LL    // 4M halves (8 batches x 512x1024)
#define ARENA_FLOATS 90767360LL

__device__ float g_arena[ARENA_FLOATS];

__device__ __forceinline__ float gelu_tanh(float v) {
    const float c0 = 0.7978845608028654f;   // sqrt(2/pi)
    float t = tanhf(c0 * (v + 0.044715f * v * v * v));
    return 0.5f * v * (1.0f + t);
}

__device__ __forceinline__ uint32_t smem_u32(const void* p) {
    return (uint32_t)__cvta_generic_to_shared(p);
}

#define CP16(dst, src) \
    asm volatile("cp.async.cg.shared.global [%0], [%1], 16;" :: "r"(dst), "l"(src))
#define CP_COMMIT() asm volatile("cp.async.commit_group;")
#define CP_WAIT0()  asm volatile("cp.async.wait_group 0;")

#define MMA_F16(c0,c1,c2,c3,a0,a1,a2,a3,b0,b1)                                \
    asm volatile("mma.sync.aligned.m16n8k16.row.col.f32.f16.f16.f32 "         \
                 "{%0,%1,%2,%3},{%4,%5,%6,%7},{%8,%9},{%0,%1,%2,%3};"         \
                 : "+f"(c0), "+f"(c1), "+f"(c2), "+f"(c3)                     \
                 : "r"(a0), "r"(a1), "r"(a2), "r"(a3), "r"(b0), "r"(b1))

#define LDSM_X4(r0,r1,r2,r3,addr)                                             \
    asm volatile("ldmatrix.sync.aligned.m8n8.x4.shared.b16 {%0,%1,%2,%3}, [%4];" \
                 : "=r"(r0), "=r"(r1), "=r"(r2), "=r"(r3) : "r"(addr))

#define LDSM_X4_T(r0,r1,r2,r3,addr)                                           \
    asm volatile("ldmatrix.sync.aligned.m8n8.x4.trans.shared.b16 {%0,%1,%2,%3}, [%4];" \
                 : "=r"(r0), "=r"(r1), "=r"(r2), "=r"(r3) : "r"(addr))

extern __shared__ __half dynh[];

// ---------------------------------------------------------------------------
// RNE-round all seven GEMM input buffers f32 -> fp16 in ONE launch.
// ---------------------------------------------------------------------------
__global__ void round_all(const float* __restrict__ x,  const float* __restrict__ Wq,
                          const float* __restrict__ Wkv,const float* __restrict__ Wp,
                          const float* __restrict__ phi,const float* __restrict__ We1,
                          const float* __restrict__ We2,
                          __half* __restrict__ xh,  __half* __restrict__ Wqh,
                          __half* __restrict__ Wkvh,__half* __restrict__ Wph,
                          __half* __restrict__ phih,__half* __restrict__ We1h,
                          __half* __restrict__ We2h)
{
    long long i = (long long)blockIdx.x * blockDim.x + threadIdx.x;
    const float* s; __half* d; long long off;
    if      (i < 1048576LL) { s = x;   d = xh;   off = i; }
    else if (i < 1310720LL) { s = Wq;  d = Wqh;  off = i - 1048576LL; }
    else if (i < 1835008LL) { s = Wkv; d = Wkvh; off = i - 1310720LL; }
    else if (i < 2097152LL) { s = Wp;  d = Wph;  off = i - 1835008LL; }
    else if (i < 2359296LL) { s = phi; d = phih; off = i - 2097152LL; }
    else if (i < 4456448LL) { s = We1; d = We1h; off = i - 2359296LL; }
    else if (i < 6553600LL) { s = We2; d = We2h; off = i - 4456448LL; }
    else return;
    float4 v = ((const float4*)s)[off];
    __half2 h01 = __floats2half2_rn(v.x, v.y);
    __half2 h23 = __floats2half2_rn(v.z, v.w);
    uint2 o;
    o.x = *(uint32_t*)&h01;
    o.y = *(uint32_t*)&h23;
    ((uint2*)d)[off] = o;
}

// ---------------------------------------------------------------------------
// fp16 tensor-core batched GEMM (m16n8k16, fp32 accum). (unchanged)
// ---------------------------------------------------------------------------
__global__ void __launch_bounds__(256, 2)
hgemm(const __half* __restrict__ A, const __half* __restrict__ Bm,
      const float* __restrict__ bias, float* __restrict__ Cf,
      __half* __restrict__ Ch,
      int M, int N, int K,
      long long sA, long long sB, long long sBias, long long sC,
      int nBmod, int act)
{
    int z = blockIdx.z;
    int zb = nBmod ? (z % nBmod) : z;
    A  += (long long)z * sA;
    Bm += (long long)zb * sB;
    if (act >= 1) bias += (long long)zb * sBias;
    if (Cf) Cf += (long long)z * sC;
    if (Ch) Ch += (long long)z * sC;

    __shared__ __half As[2][128][40];   // [m][k32 pad 40]
    __shared__ __half Bs[2][32][136];   // [k][n128 pad 136]

    int bx = blockIdx.x, by = blockIdx.y;
    int tid = threadIdx.x;
    int wid = tid >> 5;
    int lane = tid & 31;
    int g = lane >> 2;
    int j = lane & 3;
    int wm64 = (wid >> 2) * 64;
    int wn32 = (wid & 3) * 32;

    int aRow = tid >> 1;
    int aKc  = (tid & 1) * 16;
    int bRow = tid >> 3;
    int bCc  = (tid & 7) * 16;

    const __half* Ap = A + (long long)(by * 128 + aRow) * K + aKc;
    const __half* Bp = Bm + (long long)bRow * N + bx * 128 + bCc;

    uint32_t aSm = smem_u32(&As[0][aRow][aKc]);
    uint32_t bSm = smem_u32(&Bs[0][bRow][bCc]);
    const uint32_t A_BUF = 128 * 40 * 2;
    const uint32_t B_BUF = 32 * 136 * 2;

    int lmat = lane >> 3, lrow = lane & 7;
    uint32_t aFrag[4];
    #pragma unroll
    for (int mt = 0; mt < 4; mt++)
        aFrag[mt] = smem_u32(
            &As[0][wm64 + mt * 16 + (lmat & 1) * 8 + lrow][(lmat >> 1) * 8]);
    uint32_t bFrag[2];
    #pragma unroll
    for (int p = 0; p < 2; p++)
        bFrag[p] = smem_u32(
            &Bs[0][(lmat & 1) * 8 + lrow][wn32 + p * 16 + (lmat >> 1) * 8]);

    float c[4][4][4];
    #pragma unroll
    for (int mt = 0; mt < 4; mt++)
        #pragma unroll
        for (int nt = 0; nt < 4; nt++)
            #pragma unroll
            for (int r = 0; r < 4; r++) c[mt][nt][r] = 0.0f;

    CP16(aSm, Ap);            CP16(aSm + 16, Ap + 8);
    CP16(bSm, Bp);            CP16(bSm + 16, Bp + 8);
    CP_COMMIT();

    int buf = 0;
    for (int k0 = 0; k0 < K; k0 += 32) {
        CP_WAIT0();
        __syncthreads();

        if (k0 + 32 < K) {
            Ap += 32;
            Bp += (long long)32 * N;
            uint32_t aD = aSm + (buf ^ 1) * A_BUF;
            uint32_t bD = bSm + (buf ^ 1) * B_BUF;
            CP16(aD, Ap);        CP16(aD + 16, Ap + 8);
            CP16(bD, Bp);        CP16(bD + 16, Bp + 8);
            CP_COMMIT();
        }

        uint32_t aB = (uint32_t)buf * A_BUF;
        uint32_t bB = (uint32_t)buf * B_BUF;

        #pragma unroll
        for (int kk = 0; kk < 32; kk += 16) {
            uint32_t a[4][4];
            uint32_t bfr[4][2];
            #pragma unroll
            for (int mt = 0; mt < 4; mt++)
                LDSM_X4(a[mt][0], a[mt][1], a[mt][2], a[mt][3],
                        aFrag[mt] + aB + kk * 2);
            #pragma unroll
            for (int p = 0; p < 2; p++)
                LDSM_X4_T(bfr[2 * p][0], bfr[2 * p][1],
                          bfr[2 * p + 1][0], bfr[2 * p + 1][1],
                          bFrag[p] + bB + kk * 272);
            #pragma unroll
            for (int mt = 0; mt < 4; mt++)
                #pragma unroll
                for (int nt = 0; nt < 4; nt++)
                    MMA_F16(c[mt][nt][0], c[mt][nt][1], c[mt][nt][2], c[mt][nt][3],
                            a[mt][0], a[mt][1], a[mt][2], a[mt][3],
                            bfr[nt][0], bfr[nt][1]);
        }
        buf ^= 1;
    }

    #pragma unroll
    for (int mt = 0; mt < 4; mt++) {
        int r0 = by * 128 + wm64 + mt * 16 + g;
        #pragma unroll
        for (int nt = 0; nt < 4; nt++) {
            int col = bx * 128 + wn32 + nt * 8 + 2 * j;
            float b0 = 0.0f, b1 = 0.0f;
            if (act >= 1) { b0 = bias[col]; b1 = bias[col + 1]; }
            float v0 = c[mt][nt][0] + b0;
            float v1 = c[mt][nt][1] + b1;
            float v2 = c[mt][nt][2] + b0;
            float v3 = c[mt][nt][3] + b1;
            if (act == 2) {
                v0 = gelu_tanh(v0); v1 = gelu_tanh(v1);
                v2 = gelu_tanh(v2); v3 = gelu_tanh(v3);
            }
            if (Cf) {
                *(float2*)(Cf + (long long)r0 * N + col)       = make_float2(v0, v1);
                *(float2*)(Cf + (long long)(r0 + 8) * N + col) = make_float2(v2, v3);
            }
            if (Ch) {
                __half2 h01 = __floats2half2_rn(v0, v1);
                __half2 h23 = __floats2half2_rn(v2, v3);
                *(uint32_t*)(Ch + (long long)r0 * N + col)       = *(uint32_t*)&h01;
                *(uint32_t*)(Ch + (long long)(r0 + 8) * N + col) = *(uint32_t*)&h23;
            }
        }
    }
}

// ---------------------------------------------------------------------------
// Fused attention (fp16 HMMA): per (b,h), n-tile 64; cp.async double-buffered
// K/V tiles (prefetch m0+64 during compute of m0). Warp tile 32n x 16m.
// Dynamic smem 56.3KB: Kt[2][64][72] Vs[2][64][72] Qs[64][72] Ps[64][72]
// + sums[4][64] f32. Rows 144B; LDS.32 frags bank-clean.
// ---------------------------------------------------------------------------
__global__ void __launch_bounds__(256)
att_fused(const __half* __restrict__ qh, const __half* __restrict__ kvh,
          __half* __restrict__ tmp, float* __restrict__ rowrl,
          __half* __restrict__ attouth)
{
    int bh = blockIdx.y;
    int b = bh >> 4, h = bh & 15;
    int n0 = blockIdx.x * 64;

    __half* Kt = dynh;                 // [2][64][72]
    __half* Vs = dynh + 9216;          // [2][64][72]
    __half* Qs = dynh + 18432;         // [64][72]
    __half* Ps = dynh + 23040;         // [64][72]
    float* sums = (float*)(dynh + 27648);   // [4][64]

    int tid = threadIdx.x, lane = tid & 31, wid = tid >> 5;
    int g = lane >> 2, j = lane & 3;
    int wm32 = (wid >> 2) * 32;
    int wn16 = (wid & 3) * 16;

    sums[tid] = 0.0f;

    // Q tile (plain loads, once)
    for (int i = tid; i < 512; i += 256) {
        int r = i >> 3, seg = (i & 7) * 8;
        *(uint4*)&Qs[r * 72 + seg] =
            *(const uint4*)(qh + ((size_t)(b * 1024 + n0 + r) * 1024) + h * 64 + seg);
    }

    // K/V prefetch mapping: thread -> row tid>>2, 16-half segment (tid&3)*16
    int pr  = tid >> 2;
    int pse = (tid & 3) * 16;
    uint32_t kDst0 = smem_u32(&Kt[pr * 72 + pse]);
    uint32_t vDst0 = smem_u32(&Vs[pr * 72 + pse]);
    const uint32_t BUFB = 4608 * 2;    // bytes per K (or V) buffer

#define PREF(bufidx, m0v)                                                     \
    {                                                                         \
        const __half* kb = kvh + ((size_t)(b * 1024 + (m0v) + pr) * 2048) + h * 64 + pse; \
        uint32_t kd = kDst0 + (uint32_t)(bufidx) * BUFB;                      \
        uint32_t vd = vDst0 + (uint32_t)(bufidx) * BUFB;                      \
        CP16(kd, kb);       CP16(kd + 16, kb + 8);                            \
        CP16(vd, kb + 1024); CP16(vd + 16, kb + 1032);                        \
        CP_COMMIT();                                                          \
    }

    int lmat = lane >> 3, lrow = lane & 7;
    uint32_t vFragBase = smem_u32(&Vs[((lmat & 1) * 8 + lrow) * 72 + wn16 + (lmat >> 1) * 8]);

    float o[2][2][4];
    #pragma unroll
    for (int mt = 0; mt < 2; mt++)
        #pragma unroll
        for (int nt = 0; nt < 2; nt++)
            #pragma unroll
            for (int r = 0; r < 4; r++) o[mt][nt][r] = 0.0f;

    PREF(0, 0);

    int buf = 0;
    for (int m0 = 0; m0 < 1024; m0 += 64) {
        CP_WAIT0();
        __syncthreads();   // K/V[buf] landed; all warps done with previous Ps/Vs

        if (m0 + 64 < 1024) PREF(buf ^ 1, m0 + 64);

        const __half* KtB = Kt + buf * 4608;
        uint32_t vFrag = vFragBase + (uint32_t)buf * BUFB;

        // S-mma: A = Qs, B = Kt[buf]
        float c[2][2][4];
        #pragma unroll
        for (int mt = 0; mt < 2; mt++)
            #pragma unroll
            for (int nt = 0; nt < 2; nt++)
                #pragma unroll
                for (int r = 0; r < 4; r++) c[mt][nt][r] = 0.0f;

        #pragma unroll
        for (int kk = 0; kk < 64; kk += 16) {
            uint32_t a[2][4], bf[2][2];
            #pragma unroll
            for (int mt = 0; mt < 2; mt++) {
                const __half* p0 = &Qs[(wm32 + mt * 16 + g) * 72 + kk + 2 * j];
                a[mt][0] = *(const uint32_t*)p0;
                a[mt][1] = *(const uint32_t*)(p0 + 8 * 72);
                a[mt][2] = *(const uint32_t*)(p0 + 8);
                a[mt][3] = *(const uint32_t*)(p0 + 8 * 72 + 8);
            }
            #pragma unroll
            for (int nt = 0; nt < 2; nt++) {
                const __half* p0 = &KtB[(wn16 + nt * 8 + g) * 72 + kk + 2 * j];
                bf[nt][0] = *(const uint32_t*)p0;
                bf[nt][1] = *(const uint32_t*)(p0 + 8);
            }
            #pragma unroll
            for (int mt = 0; mt < 2; mt++)
                #pragma unroll
                for (int nt = 0; nt < 2; nt++)
                    MMA_F16(c[mt][nt][0], c[mt][nt][1], c[mt][nt][2], c[mt][nt][3],
                            a[mt][0], a[mt][1], a[mt][2], a[mt][3],
                            bf[nt][0], bf[nt][1]);
        }

        // E = exp(0.125*S) -> fp16 (tmp, Ps); row sums of fp16 values
        #pragma unroll
        for (int mt = 0; mt < 2; mt++) {
            int r1 = wm32 + mt * 16 + g;
            float eA = 0.0f, eB = 0.0f;
            #pragma unroll
            for (int nt = 0; nt < 2; nt++) {
                int col = wn16 + nt * 8 + 2 * j;
                float e0 = __expf(0.125f * c[mt][nt][0]);
                float e1 = __expf(0.125f * c[mt][nt][1]);
                float e2 = __expf(0.125f * c[mt][nt][2]);
                float e3 = __expf(0.125f * c[mt][nt][3]);
                __half2 h01 = __floats2half2_rn(e0, e1);
                __half2 h23 = __floats2half2_rn(e2, e3);
                size_t idx = ((size_t)bh * 1024 + n0 + r1) * 1024 + m0 + col;
                __stcs((unsigned int*)(tmp + idx),            *(uint32_t*)&h01);
                __stcs((unsigned int*)(tmp + idx + 8 * 1024), *(uint32_t*)&h23);
                *(uint32_t*)&Ps[r1 * 72 + col]       = *(uint32_t*)&h01;
                *(uint32_t*)&Ps[(r1 + 8) * 72 + col] = *(uint32_t*)&h23;
                float2 f01 = __half22float2(h01);
                float2 f23 = __half22float2(h23);
                eA += f01.x + f01.y;
                eB += f23.x + f23.y;
            }
            eA += __shfl_xor_sync(0xffffffffu, eA, 1);
            eA += __shfl_xor_sync(0xffffffffu, eA, 2);
            eB += __shfl_xor_sync(0xffffffffu, eB, 1);
            eB += __shfl_xor_sync(0xffffffffu, eB, 2);
            if (j == 0) {
                sums[(wn16 >> 4) * 64 + r1]     += eA;
                sums[(wn16 >> 4) * 64 + r1 + 8] += eB;
            }
        }
        __syncthreads();

        // PV-mma: A = Ps, B = Vs[buf] (ldmatrix.trans)
        #pragma unroll
        for (int kk = 0; kk < 64; kk += 16) {
            uint32_t a[2][4], bf[2][2];
            #pragma unroll
            for (int mt = 0; mt < 2; mt++) {
                const __half* p0 = &Ps[(wm32 + mt * 16 + g) * 72 + kk + 2 * j];
                a[mt][0] = *(const uint32_t*)p0;
                a[mt][1] = *(const uint32_t*)(p0 + 8 * 72);
                a[mt][2] = *(const uint32_t*)(p0 + 8);
                a[mt][3] = *(const uint32_t*)(p0 + 8 * 72 + 8);
            }
            LDSM_X4_T(bf[0][0], bf[0][1], bf[1][0], bf[1][1],
                      vFrag + kk * 144);
            #pragma unroll
            for (int mt = 0; mt < 2; mt++)
                #pragma unroll
                for (int nt = 0; nt < 2; nt++)
                    MMA_F16(o[mt][nt][0], o[mt][nt][1], o[mt][nt][2], o[mt][nt][3],
                            a[mt][0], a[mt][1], a[mt][2], a[mt][3],
                            bf[nt][0], bf[nt][1]);
        }
        buf ^= 1;
    }

    __syncthreads();
    if (tid < 64) {
        float tot = sums[tid] + sums[64 + tid] + sums[128 + tid] + sums[192 + tid];
        float r = 1.0f / tot;
        sums[tid] = r;
        rowrl[(size_t)bh * 1024 + n0 + tid] = r;
    }
    __syncthreads();

    #pragma unroll
    for (int mt = 0; mt < 2; mt++) {
        int r1 = wm32 + mt * 16 + g;
        float rlA = sums[r1], rlB = sums[r1 + 8];
        #pragma unroll
        for (int nt = 0; nt < 2; nt++) {
            int col = wn16 + nt * 8 + 2 * j;
            __half* base = attouth + ((size_t)(b * 1024 + n0 + r1) * 1024) + h * 64 + col;
            __half2 h01 = __floats2half2_rn(o[mt][nt][0] * rlA, o[mt][nt][1] * rlA);
            __half2 h23 = __floats2half2_rn(o[mt][nt][2] * rlB, o[mt][nt][3] * rlB);
            *(uint32_t*)base              = *(uint32_t*)&h01;
            *(uint32_t*)(base + 8 * 1024) = *(uint32_t*)&h23;
        }
    }
#undef PREF
}

// ---------------------------------------------------------------------------
// Normalize + transpose: out(b,n,m,h) = E_fp16(b,h,n,m) * rl(b,h,n).
// ---------------------------------------------------------------------------
__global__ void attn_tr(const __half* __restrict__ tmp, const float* __restrict__ rowrl,
                        float* __restrict__ outAttn)
{
    int b = blockIdx.y;
    int n = blockIdx.x;
    __shared__ float T[16][257];
    __shared__ float rl_s[16];
    int tid = threadIdx.x;
    if (tid < 16) rl_s[tid] = rowrl[(size_t)(b * 16 + tid) * 1024 + n];
    __syncthreads();

    for (int m0 = 0; m0 < 1024; m0 += 256) {
        for (int i = tid; i < 512; i += 256) {
            int hh = i & 15;
            int mm = (i >> 4) * 8;
            uint4 raw = __ldcs((const uint4*)
                (tmp + ((size_t)(b * 16 + hh) * 1024 + n) * 1024 + m0 + mm));
            float rl = rl_s[hh];
            __half2 v0 = *(__half2*)&raw.x;
            __half2 v1 = *(__half2*)&raw.y;
            __half2 v2 = *(__half2*)&raw.z;
            __half2 v3 = *(__half2*)&raw.w;
            float2 f0 = __half22float2(v0);
            float2 f1 = __half22float2(v1);
            float2 f2 = __half22float2(v2);
            float2 f3 = __half22float2(v3);
            float* tr = &T[hh][mm];
            tr[0] = f0.x * rl; tr[1] = f0.y * rl;
            tr[2] = f1.x * rl; tr[3] = f1.y * rl;
            tr[4] = f2.x * rl; tr[5] = f2.y * rl;
            tr[6] = f3.x * rl; tr[7] = f3.y * rl;
        }
        __syncthreads();
        float* dst = outAttn + ((size_t)(b * 1024 + n) * 1024 + m0 + tid) * 16;
        #pragma unroll
        for (int k = 0; k < 16; k += 4) {
            __stcs((float4*)(dst + k),
                   make_float4(T[k][tid], T[k + 1][tid], T[k + 2][tid], T[k + 3][tid]));
        }
        __syncthreads();
    }
}

// ---------------------------------------------------------------------------
// Row softmax over contiguous 1024 (combine weights), fp16 out.
// ---------------------------------------------------------------------------
__global__ void row_softmax(const float* __restrict__ in, __half* __restrict__ outp)
{
    size_t row = blockIdx.x;
    const float4* L = (const float4*)(in + row * 1024);
    int t = threadIdx.x;
    float4 v = L[t];
    float mx = fmaxf(fmaxf(v.x, v.y), fmaxf(v.z, v.w));
    __shared__ float smA[8], smB[8];
    #pragma unroll
    for (int off = 16; off; off >>= 1) mx = fmaxf(mx, __shfl_xor_sync(0xffffffffu, mx, off));
    if ((t & 31) == 0) smA[t >> 5] = mx;
    __syncthreads();
    mx = smA[0];
    #pragma unroll
    for (int w = 1; w < 8; w++) mx = fmaxf(mx, smA[w]);
    float e0 = __expf(v.x - mx), e1 = __expf(v.y - mx);
    float e2 = __expf(v.z - mx), e3 = __expf(v.w - mx);
    float s = e0 + e1 + e2 + e3;
    #pragma unroll
    for (int off = 16; off; off >>= 1) s += __shfl_xor_sync(0xffffffffu, s, off);
    if ((t & 31) == 0) smB[t >> 5] = s;
    __syncthreads();
    s = 0.0f;
    #pragma unroll
    for (int w = 0; w < 8; w++) s += smB[w];
    float r = 1.0f / s;
    __half2 h01 = __floats2half2_rn(e0 * r, e1 * r);
    __half2 h23 = __floats2half2_rn(e2 * r, e3 * r);
    uint2 o;
    o.x = *(uint32_t*)&h01;
    o.y = *(uint32_t*)&h23;
    ((uint2*)(outp + row * 1024))[t] = o;
}

// ---------------------------------------------------------------------------
// Dispatch softmax over token axis n, written TRANSPOSED, fp16 out.
// ---------------------------------------------------------------------------
__global__ void disp_softmax(const float* __restrict__ logits, __half* __restrict__ dispT)
{
    int b = blockIdx.y;
    int c0 = blockIdx.x * 64;
    const float* L = logits + (size_t)b * 1048576;
    __half* O = dispT + (size_t)b * 1048576;
    int tid = threadIdx.x;
    int tx = tid & 63, ty = tid >> 6;   // 4 x 64
    int col = c0 + tx;

    __shared__ float red[4][64];
    float mx = -1e30f;
    for (int n = ty; n < 1024; n += 4) mx = fmaxf(mx, L[(size_t)n * 1024 + col]);
    red[ty][tx] = mx;
    __syncthreads();
    mx = fmaxf(fmaxf(red[0][tx], red[1][tx]), fmaxf(red[2][tx], red[3][tx]));
    __syncthreads();
    float s = 0.0f;
    for (int n = ty; n < 1024; n += 4) s += __expf(L[(size_t)n * 1024 + col] - mx);
    red[ty][tx] = s;
    __syncthreads();
    s = red[0][tx] + red[1][tx] + red[2][tx] + red[3][tx];
    float rinv = 1.0f / s;
    __syncthreads();

    __shared__ float T[64][65];
    for (int n0 = 0; n0 < 1024; n0 += 64) {
        for (int n = ty; n < 64; n += 4)
            T[tx][n] = __expf(L[(size_t)(n0 + n) * 1024 + col] - mx) * rinv;
        __syncthreads();
        int cl = tid >> 2;
        int nl = (tid & 3) * 16;
        __half* dst = O + (size_t)(c0 + cl) * 1024 + n0 + nl;
        #pragma unroll
        for (int k = 0; k < 16; k += 4) {
            __half2 h01 = __floats2half2_rn(T[cl][nl + k],     T[cl][nl + k + 1]);
            __half2 h23 = __floats2half2_rn(T[cl][nl + k + 2], T[cl][nl + k + 3]);
            uint2 o;
            o.x = *(uint32_t*)&h01;
            o.y = *(uint32_t*)&h23;
            *(uint2*)(dst + k) = o;
        }
        __syncthreads();
    }
}

// ---------------------------------------------------------------------------
// Fused residual + LayerNorm: out = LN(a + coefb * bsrc) * g + beta.
// If outH != null: values RNE-rounded to fp16, written to BOTH outputs.
// ---------------------------------------------------------------------------
__global__ void ln_res(const float* __restrict__ a, const float* __restrict__ bsrc,
                       float coefb, const float* __restrict__ g,
                       const float* __restrict__ beta, float* __restrict__ outp,
                       __half* __restrict__ outH)
{
    size_t row = blockIdx.x;
    int t = threadIdx.x;
    float4 av = ((const float4*)(a + row * 1024))[t];
    float4 bv = ((const float4*)(bsrc + row * 1024))[t];
    float x0 = av.x + coefb * bv.x;
    float x1 = av.y + coefb * bv.y;
    float x2 = av.z + coefb * bv.z;
    float x3 = av.w + coefb * bv.w;
    float s = x0 + x1 + x2 + x3;
    float q = x0 * x0 + x1 * x1 + x2 * x2 + x3 * x3;
    __shared__ float smA[8], smB[8];
    #pragma unroll
    for (int off = 16; off; off >>= 1) {
        s += __shfl_xor_sync(0xffffffffu, s, off);
        q += __shfl_xor_sync(0xffffffffu, q, off);
    }
    if ((t & 31) == 0) { smA[t >> 5] = s; smB[t >> 5] = q; }
    __syncthreads();
    s = 0.0f; q = 0.0f;
    #pragma unroll
    for (int w = 0; w < 8; w++) { s += smA[w]; q += smB[w]; }
    float mu = s * (1.0f / 1024.0f);
    float var = q * (1.0f / 1024.0f) - mu * mu;
    float rs = rsqrtf(var + 1e-5f);
    float4 gv = ((const float4*)g)[t];
    float4 btv = ((const float4*)beta)[t];
    float4 out4;
    out4.x = (x0 - mu) * rs * gv.x + btv.x;
    out4.y = (x1 - mu) * rs * gv.y + btv.y;
    out4.z = (x2 - mu) * rs * gv.z + btv.z;
    out4.w = (x3 - mu) * rs * gv.w + btv.w;
    if (outH) {
        __half2 h01 = __floats2half2_rn(out4.x, out4.y);
        __half2 h23 = __floats2half2_rn(out4.z, out4.w);
        uint2 o;
        o.x = *(uint32_t*)&h01;
        o.y = *(uint32_t*)&h23;
        ((uint2*)(outH + row * 1024))[t] = o;
        float2 f01 = __half22float2(h01);
        float2 f23 = __half22float2(h23);
        out4.x = f01.x; out4.y = f01.y; out4.z = f23.x; out4.w = f23.y;
    }
    ((float4*)(outp + row * 1024))[t] = out4;
}

// ---------------------------------------------------------------------------
// Launcher. attn_tr on a side stream overlapping proj->LN->MoE (joined
// before final LN). Stream/events created once.
// ---------------------------------------------------------------------------
static cudaStream_t g_side = nullptr;
static cudaEvent_t  g_evA  = nullptr;
static cudaEvent_t  g_evB  = nullptr;

extern "C" void kernel_launch(void* const* d_in, const int* in_sizes, int n_in,
                              void* d_out, int out_size)
{
    const float* x   = (const float*)d_in[0];
    const float* Wq  = (const float*)d_in[1];
    const float* bq  = (const float*)d_in[2];
    const float* Wkv = (const float*)d_in[3];
    const float* bkv = (const float*)d_in[4];
    const float* Wp  = (const float*)d_in[5];
    const float* bp  = (const float*)d_in[6];
    const float* g1  = (const float*)d_in[7];
    const float* b1  = (const float*)d_in[8];
    const float* phi = (const float*)d_in[9];
    const float* We1 = (const float*)d_in[10];
    const float* be1 = (const float*)d_in[11];
    const float* We2 = (const float*)d_in[12];
    const float* be2 = (const float*)d_in[13];
    const float* g2  = (const float*)d_in[14];
    const float* b2  = (const float*)d_in[15];

    if (!g_side) {
        cudaStreamCreateWithFlags(&g_side, cudaStreamNonBlocking);
        cudaEventCreateWithFlags(&g_evA, cudaEventDisableTiming);
        cudaEventCreateWithFlags(&g_evB, cudaEventDisableTiming);
    }

    float* arena = nullptr;
    cudaGetSymbolAddress((void**)&arena, g_arena);

    __half* tmp     = (__half*)(arena + OFF_TMP);
    float*  proj    = arena + OFF_PROJ;
    float*  x1      = arena + OFF_X1;
    float*  logits  = arena + OFF_LOGITS;
    float*  moeout  = arena + OFF_MOE;
    float*  rl      = arena + OFF_RL;
    __half* xh      = (__half*)(arena + OFF_XH);
    __half* Wqh     = (__half*)(arena + OFF_WQH);
    __half* Wkvh    = (__half*)(arena + OFF_WKVH);
    __half* Wph     = (__half*)(arena + OFF_WPH);
    __half* phih    = (__half*)(arena + OFF_PHIH);
    __half* We1h    = (__half*)(arena + OFF_WE1H);
    __half* We2h    = (__half*)(arena + OFF_WE2H);
    __half* qh      = (__half*)(arena + OFF_QH);
    __half* kvh     = (__half*)(arena + OFF_KVH);
    __half* attouth = (__half*)(arena + OFF_ATTOUTH);
    __half* x1h     = (__half*)(arena + OFF_X1H);
    __half* dispTh  = (__half*)(arena + OFF_DISPTH);
    __half* combh   = (__half*)(arena + OFF_COMBH);
    __half* slotsh  = (__half*)(arena + OFF_SLOTSH);
    __half* hh      = (__half*)(arena + OFF_HH);
    __half* ymoeh   = (__half*)(arena + OFF_YMOEH);

    float* out = (float*)d_out;
    float* outAttn = out + 4194304;

    const int ATT_SMEM = 56320;   // 28160 halves
    cudaFuncSetAttribute(att_fused, cudaFuncAttributeMaxDynamicSharedMemorySize, ATT_SMEM);

    dim3 T(256);

    // prep: RNE-round all GEMM inputs to fp16, one launch
    round_all<<<25600, T>>>(x, Wq, Wkv, Wp, phi, We1, We2,
                            xh, Wqh, Wkvh, Wph, phih, We1h, We2h);

    // q = x @ Wq + bq          (4096x1024x1024) -> fp16
    hgemm<<<dim3(8, 32, 1), T>>>(xh, Wqh, bq, nullptr, qh, 4096, 1024, 1024,
                                 0, 0, 0, 0, 1, 1);
    // kv = x @ Wkv + bkv       (4096x2048x1024) -> fp16
    hgemm<<<dim3(16, 32, 1), T>>>(xh, Wkvh, bkv, nullptr, kvh, 4096, 2048, 1024,
                                  0, 0, 0, 0, 1, 1);

    // fused attention (cp.async K/V pipeline)
    att_fused<<<dim3(16, 64), T, ATT_SMEM>>>(qh, kvh, tmp, rl, attouth);

    // fork: attn_tr on side stream
    cudaEventRecord(g_evA, 0);
    cudaStreamWaitEvent(g_side, g_evA, 0);
    attn_tr<<<dim3(1024, 4), T, 0, g_side>>>(tmp, rl, outAttn);
    cudaEventRecord(g_evB, g_side);

    // out-proj (f32) + residual LN (x1 f32 + fp16)   [main stream]
    hgemm<<<dim3(8, 32, 1), T>>>(attouth, Wph, bp, proj, nullptr, 4096, 1024, 1024,
                                 0, 0, 0, 0, 1, 1);
    ln_res<<<4096, T>>>(proj, x, 1.0f, g1, b1, x1, x1h);

    // soft-MoE
    hgemm<<<dim3(8, 32, 1), T>>>(x1h, phih, nullptr, logits, nullptr, 4096, 1024, 1024,
                                 0, 0, 0, 0, 1, 0);
    row_softmax<<<4096, T>>>(logits, combh);
    disp_softmax<<<dim3(16, 4), T>>>(logits, dispTh);

    // slots[b] = dispT[b] @ x1[b] -> fp16
    hgemm<<<dim3(8, 8, 4), T>>>(dispTh, x1h, nullptr, nullptr, slotsh, 1024, 1024, 1024,
                                1048576, 1048576, 0, 1048576, 0, 0);
    // h = gelu(slots @ We1[e] + be1[e]) -> fp16
    hgemm<<<dim3(32, 4, 8), T>>>(slotsh, We1h, be1, nullptr, hh, 512, 4096, 1024,
                                 524288, 4194304, 4096, 2097152, 2, 2);
    // y = h @ We2[e] + be2[e] -> fp16
    hgemm<<<dim3(8, 4, 8), T>>>(hh, We2h, be2, nullptr, ymoeh, 512, 1024, 4096,
                                2097152, 4194304, 1024, 524288, 2, 1);
    // moe_out[b] = comb[b] @ ymoe[b] -> f32
    hgemm<<<dim3(8, 8, 4), T>>>(combh, ymoeh, nullptr, moeout, nullptr, 1024, 1024, 1024,
                                1048576, 1048576, 0, 1048576, 0, 0);

    // join side stream, then final LN
    cudaStreamWaitEvent(0, g_evB, 0);
    ln_res<<<4096, T>>>(moeout, x1, 2.0f, g2, b2, out, nullptr);
}

// round 16
// speedup vs baseline: 1.7487x; 1.7487x over previous
#include <cuda_runtime.h>
#include <cuda_fp16.h>
#include <math.h>
#include <stdint.h>

// ---------------------------------------------------------------------------
// Problem constants
//   B=4, SEQ=1024, DIM=1024, HEADS=16, N_EXP=2, SLOTS=512, HID=4096
// Output: [ y : 4*1024*1024 f32 ][ attn : 4*1024*1024*16 f32 ]
// All GEMM/attention operands fp16 (RNE-rounded at producer), fp32 accumulate.
// qkv fused: W_qkv [1024x3072] (q|k|v), out qkv [4096x3072].
// ---------------------------------------------------------------------------

// arena offsets in FLOAT units (fp16 buffers occupy elem_count/2 float slots)
#define OFF_TMP      0LL           // 64M halves = 32M floats
#define OFF_PROJ     33554432LL    // 4M f32
#define OFF_X1       37748736LL    // 4M f32
#define OFF_LOGITS   41943040LL    // 4M f32
#define OFF_MOE      46137344LL    // 4M f32
#define OFF_RL       50331648LL    // 64K f32
#define OFF_XH       50397184LL    // 4M halves
#define OFF_WQKVH    52494336LL    // 3M halves (1024 x 3072, q|k|v)
#define OFF_WPH      54067200LL    // 1M halves
#define OFF_PHIH     54591488LL    // 1M halves
#define OFF_WE1H     55115776LL    // 8M halves
#define OFF_WE2H     59310080LL    // 8M halves
#define OFF_QKVH     63504384LL    // 12M halves (4096 x 3072)
#define OFF_ATTOUTH  69795840LL    // 4M halves
#define OFF_X1H      71892992LL    // 4M halves
#define OFF_DISPTH   73990144LL    // 4M halves
#define OFF_COMBH    76087296LL    // 4M halves
#define OFF_SLOTSH   78184448LL    // 4M halves
#define OFF_HH       80281600LL    // 16M halves
#define OFF_YMOEH    88670208LL    // 4M halves
#define OFF_BQKV     90767360LL    // 3072 f32 (bq | bkv)
#define ARENA_FLOATS 90770432LL

__device__ float g_arena[ARENA_FLOATS];

__device__ __forceinline__ float gelu_tanh(float v) {
    const float c0 = 0.7978845608028654f;   // sqrt(2/pi)
    float t = tanhf(c0 * (v + 0.044715f * v * v * v));
    return 0.5f * v * (1.0f + t);
}

__device__ __forceinline__ uint32_t smem_u32(const void* p) {
    return (uint32_t)__cvta_generic_to_shared(p);
}

#define CP16(dst, src) \
    asm volatile("cp.async.cg.shared.global [%0], [%1], 16;" :: "r"(dst), "l"(src))
#define CP_COMMIT() asm volatile("cp.async.commit_group;")
#define CP_WAIT0()  asm volatile("cp.async.wait_group 0;")

#define MMA_F16(c0,c1,c2,c3,a0,a1,a2,a3,b0,b1)                                \
    asm volatile("mma.sync.aligned.m16n8k16.row.col.f32.f16.f16.f32 "         \
                 "{%0,%1,%2,%3},{%4,%5,%6,%7},{%8,%9},{%0,%1,%2,%3};"         \
                 : "+f"(c0), "+f"(c1), "+f"(c2), "+f"(c3)                     \
                 : "r"(a0), "r"(a1), "r"(a2), "r"(a3), "r"(b0), "r"(b1))

#define LDSM_X4(r0,r1,r2,r3,addr)                                             \
    asm volatile("ldmatrix.sync.aligned.m8n8.x4.shared.b16 {%0,%1,%2,%3}, [%4];" \
                 : "=r"(r0), "=r"(r1), "=r"(r2), "=r"(r3) : "r"(addr))

#define LDSM_X4_T(r0,r1,r2,r3,addr)                                           \
    asm volatile("ldmatrix.sync.aligned.m8n8.x4.trans.shared.b16 {%0,%1,%2,%3}, [%4];" \
                 : "=r"(r0), "=r"(r1), "=r"(r2), "=r"(r3) : "r"(addr))

// ---------------------------------------------------------------------------
// Prep: RNE-round GEMM inputs f32 -> fp16 in ONE launch.
// Wq/Wkv interleave into Wqkvh rows (q cols 0..1023, kv cols 1024..3071);
// bq|bkv concatenated (f32) into bqkv.
// Segments (float4 units): x 1048576 | Wq 262144 | Wkv 524288 | Wp 262144
//   | phi 262144 | We1 2097152 | We2 2097152 | bias 768  (total 6554368)
// ---------------------------------------------------------------------------
__global__ void round_all(const float* __restrict__ x,  const float* __restrict__ Wq,
                          const float* __restrict__ Wkv,const float* __restrict__ Wp,
                          const float* __restrict__ phi,const float* __restrict__ We1,
                          const float* __restrict__ We2,
                          const float* __restrict__ bq, const float* __restrict__ bkv,
                          __half* __restrict__ xh,  __half* __restrict__ Wqkvh,
                          __half* __restrict__ Wph,
                          __half* __restrict__ phih,__half* __restrict__ We1h,
                          __half* __restrict__ We2h,
                          float* __restrict__ bqkv)
{
    long long i = (long long)blockIdx.x * blockDim.x + threadIdx.x;
    const float* s; __half* d; long long off;
    if (i < 1048576LL)      { s = x;   d = xh;   off = i; }
    else if (i < 1310720LL) {          // Wq -> Wqkvh cols 0..1023
        long long o = i - 1048576LL;
        long long row = o >> 8, c = o & 255;
        s = Wq; d = Wqkvh; off = -1;
        float4 v = ((const float4*)s)[o];
        __half2 h01 = __floats2half2_rn(v.x, v.y);
        __half2 h23 = __floats2half2_rn(v.z, v.w);
        uint2 w; w.x = *(uint32_t*)&h01; w.y = *(uint32_t*)&h23;
        ((uint2*)d)[row * 768 + c] = w;
        return;
    }
    else if (i < 1835008LL) {          // Wkv -> Wqkvh cols 1024..3071
        long long o = i - 1310720LL;
        long long row = o >> 9, c = o & 511;
        float4 v = ((const float4*)Wkv)[o];
        __half2 h01 = __floats2half2_rn(v.x, v.y);
        __half2 h23 = __floats2half2_rn(v.z, v.w);
        uint2 w; w.x = *(uint32_t*)&h01; w.y = *(uint32_t*)&h23;
        ((uint2*)Wqkvh)[row * 768 + 256 + c] = w;
        return;
    }
    else if (i < 2097152LL) { s = Wp;  d = Wph;  off = i - 1835008LL; }
    else if (i < 2359296LL) { s = phi; d = phih; off = i - 2097152LL; }
    else if (i < 4456448LL) { s = We1; d = We1h; off = i - 2359296LL; }
    else if (i < 6553600LL) { s = We2; d = We2h; off = i - 4456448LL; }
    else if (i < 6554368LL) {          // bias concat (f32 -> f32)
        long long o = i - 6553600LL;
        float4 v = (o < 256) ? ((const float4*)bq)[o] : ((const float4*)bkv)[o - 256];
        ((float4*)bqkv)[o] = v;
        return;
    }
    else return;
    float4 v = ((const float4*)s)[off];
    __half2 h01 = __floats2half2_rn(v.x, v.y);
    __half2 h23 = __floats2half2_rn(v.z, v.w);
    uint2 o2;
    o2.x = *(uint32_t*)&h01;
    o2.y = *(uint32_t*)&h23;
    ((uint2*)d)[off] = o2;
}

// ---------------------------------------------------------------------------
// fp16 tensor-core batched GEMM (m16n8k16, fp32 accum). (R12/R14 version)
// ---------------------------------------------------------------------------
__global__ void __launch_bounds__(256, 2)
hgemm(const __half* __restrict__ A, const __half* __restrict__ Bm,
      const float* __restrict__ bias, float* __restrict__ Cf,
      __half* __restrict__ Ch,
      int M, int N, int K,
      long long sA, long long sB, long long sBias, long long sC,
      int nBmod, int act)
{
    int z = blockIdx.z;
    int zb = nBmod ? (z % nBmod) : z;
    A  += (long long)z * sA;
    Bm += (long long)zb * sB;
    if (act >= 1) bias += (long long)zb * sBias;
    if (Cf) Cf += (long long)z * sC;
    if (Ch) Ch += (long long)z * sC;

    __shared__ __half As[2][128][40];   // [m][k32 pad 40]
    __shared__ __half Bs[2][32][136];   // [k][n128 pad 136]

    int bx = blockIdx.x, by = blockIdx.y;
    int tid = threadIdx.x;
    int wid = tid >> 5;
    int lane = tid & 31;
    int g = lane >> 2;
    int j = lane & 3;
    int wm64 = (wid >> 2) * 64;
    int wn32 = (wid & 3) * 32;

    int aRow = tid >> 1;
    int aKc  = (tid & 1) * 16;
    int bRow = tid >> 3;
    int bCc  = (tid & 7) * 16;

    const __half* Ap = A + (long long)(by * 128 + aRow) * K + aKc;
    const __half* Bp = Bm + (long long)bRow * N + bx * 128 + bCc;

    uint32_t aSm = smem_u32(&As[0][aRow][aKc]);
    uint32_t bSm = smem_u32(&Bs[0][bRow][bCc]);
    const uint32_t A_BUF = 128 * 40 * 2;
    const uint32_t B_BUF = 32 * 136 * 2;

    int lmat = lane >> 3, lrow = lane & 7;
    uint32_t aFrag[4];
    #pragma unroll
    for (int mt = 0; mt < 4; mt++)
        aFrag[mt] = smem_u32(
            &As[0][wm64 + mt * 16 + (lmat & 1) * 8 + lrow][(lmat >> 1) * 8]);
    uint32_t bFrag[2];
    #pragma unroll
    for (int p = 0; p < 2; p++)
        bFrag[p] = smem_u32(
            &Bs[0][(lmat & 1) * 8 + lrow][wn32 + p * 16 + (lmat >> 1) * 8]);

    float c[4][4][4];
    #pragma unroll
    for (int mt = 0; mt < 4; mt++)
        #pragma unroll
        for (int nt = 0; nt < 4; nt++)
            #pragma unroll
            for (int r = 0; r < 4; r++) c[mt][nt][r] = 0.0f;

    CP16(aSm, Ap);            CP16(aSm + 16, Ap + 8);
    CP16(bSm, Bp);            CP16(bSm + 16, Bp + 8);
    CP_COMMIT();

    int buf = 0;
    for (int k0 = 0; k0 < K; k0 += 32) {
        CP_WAIT0();
        __syncthreads();

        if (k0 + 32 < K) {
            Ap += 32;
            Bp += (long long)32 * N;
            uint32_t aD = aSm + (buf ^ 1) * A_BUF;
            uint32_t bD = bSm + (buf ^ 1) * B_BUF;
            CP16(aD, Ap);        CP16(aD + 16, Ap + 8);
            CP16(bD, Bp);        CP16(bD + 16, Bp + 8);
            CP_COMMIT();
        }

        uint32_t aB = (uint32_t)buf * A_BUF;
        uint32_t bB = (uint32_t)buf * B_BUF;

        #pragma unroll
        for (int kk = 0; kk < 32; kk += 16) {
            uint32_t a[4][4];
            uint32_t bfr[4][2];
            #pragma unroll
            for (int mt = 0; mt < 4; mt++)
                LDSM_X4(a[mt][0], a[mt][1], a[mt][2], a[mt][3],
                        aFrag[mt] + aB + kk * 2);
            #pragma unroll
            for (int p = 0; p < 2; p++)
                LDSM_X4_T(bfr[2 * p][0], bfr[2 * p][1],
                          bfr[2 * p + 1][0], bfr[2 * p + 1][1],
                          bFrag[p] + bB + kk * 272);
            #pragma unroll
            for (int mt = 0; mt < 4; mt++)
                #pragma unroll
                for (int nt = 0; nt < 4; nt++)
                    MMA_F16(c[mt][nt][0], c[mt][nt][1], c[mt][nt][2], c[mt][nt][3],
                            a[mt][0], a[mt][1], a[mt][2], a[mt][3],
                            bfr[nt][0], bfr[nt][1]);
        }
        buf ^= 1;
    }

    #pragma unroll
    for (int mt = 0; mt < 4; mt++) {
        int r0 = by * 128 + wm64 + mt * 16 + g;
        #pragma unroll
        for (int nt = 0; nt < 4; nt++) {
            int col = bx * 128 + wn32 + nt * 8 + 2 * j;
            float b0 = 0.0f, b1 = 0.0f;
            if (act >= 1) { b0 = bias[col]; b1 = bias[col + 1]; }
            float v0 = c[mt][nt][0] + b0;
            float v1 = c[mt][nt][1] + b1;
            float v2 = c[mt][nt][2] + b0;
            float v3 = c[mt][nt][3] + b1;
            if (act == 2) {
                v0 = gelu_tanh(v0); v1 = gelu_tanh(v1);
                v2 = gelu_tanh(v2); v3 = gelu_tanh(v3);
            }
            if (Cf) {
                *(float2*)(Cf + (long long)r0 * N + col)       = make_float2(v0, v1);
                *(float2*)(Cf + (long long)(r0 + 8) * N + col) = make_float2(v2, v3);
            }
            if (Ch) {
                __half2 h01 = __floats2half2_rn(v0, v1);
                __half2 h23 = __floats2half2_rn(v2, v3);
                *(uint32_t*)(Ch + (long long)r0 * N + col)       = *(uint32_t*)&h01;
                *(uint32_t*)(Ch + (long long)(r0 + 8) * N + col) = *(uint32_t*)&h23;
            }
        }
    }
}

// ---------------------------------------------------------------------------
// Fused attention (fp16 HMMA): per (b,h), n-tile 64. (R12 version, plain
// loads, static smem pad-72 rows.) qkv layout: token stride 3072, q|k|v.
// S = Q K^T; E = exp(0.125*S) -> fp16 (tmp + smem Ps); O = (E@V)/rowsum.
// ---------------------------------------------------------------------------
__global__ void __launch_bounds__(256)
att_fused(const __half* __restrict__ qkvh,
          __half* __restrict__ tmp, float* __restrict__ rowrl,
          __half* __restrict__ attouth)
{
    int bh = blockIdx.y;
    int b = bh >> 4, h = bh & 15;
    int n0 = blockIdx.x * 64;

    __shared__ __half Qs[64][72];   // [n][d]
    __shared__ __half Kt[64][72];   // [m][d]
    __shared__ __half Vs[64][72];   // [m][d]
    __shared__ __half Ps[64][72];   // [n][m-chunk]
    __shared__ float sums[4][64];

    int tid = threadIdx.x, lane = tid & 31, wid = tid >> 5;
    int g = lane >> 2, j = lane & 3;
    int wm32 = (wid >> 2) * 32;
    int wn16 = (wid & 3) * 16;

    sums[tid >> 6][tid & 63] = 0.0f;

    for (int i = tid; i < 512; i += 256) {
        int r = i >> 3, seg = (i & 7) * 8;
        *(uint4*)&Qs[r][seg] =
            *(const uint4*)(qkvh + ((size_t)(b * 1024 + n0 + r) * 3072) + h * 64 + seg);
    }

    int lmat = lane >> 3, lrow = lane & 7;
    uint32_t vFrag = smem_u32(&Vs[(lmat & 1) * 8 + lrow][wn16 + (lmat >> 1) * 8]);

    float o[2][2][4];
    #pragma unroll
    for (int mt = 0; mt < 2; mt++)
        #pragma unroll
        for (int nt = 0; nt < 2; nt++)
            #pragma unroll
            for (int r = 0; r < 4; r++) o[mt][nt][r] = 0.0f;

    for (int m0 = 0; m0 < 1024; m0 += 64) {
        __syncthreads();
        for (int i = tid; i < 512; i += 256) {
            int r = i >> 3, seg = (i & 7) * 8;
            const __half* kb = qkvh + ((size_t)(b * 1024 + m0 + r) * 3072) + 1024 + h * 64 + seg;
            *(uint4*)&Kt[r][seg] = *(const uint4*)kb;
            *(uint4*)&Vs[r][seg] = *(const uint4*)(kb + 1024);
        }
        __syncthreads();

        // S-mma
        float c[2][2][4];
        #pragma unroll
        for (int mt = 0; mt < 2; mt++)
            #pragma unroll
            for (int nt = 0; nt < 2; nt++)
                #pragma unroll
                for (int r = 0; r < 4; r++) c[mt][nt][r] = 0.0f;

        #pragma unroll
        for (int kk = 0; kk < 64; kk += 16) {
            uint32_t a[2][4], bf[2][2];
            #pragma unroll
            for (int mt = 0; mt < 2; mt++) {
                const __half* p0 = &Qs[wm32 + mt * 16 + g][kk + 2 * j];
                a[mt][0] = *(const uint32_t*)p0;
                a[mt][1] = *(const uint32_t*)(p0 + 8 * 72);
                a[mt][2] = *(const uint32_t*)(p0 + 8);
                a[mt][3] = *(const uint32_t*)(p0 + 8 * 72 + 8);
            }
            #pragma unroll
            for (int nt = 0; nt < 2; nt++) {
                const __half* p0 = &Kt[wn16 + nt * 8 + g][kk + 2 * j];
                bf[nt][0] = *(const uint32_t*)p0;
                bf[nt][1] = *(const uint32_t*)(p0 + 8);
            }
            #pragma unroll
            for (int mt = 0; mt < 2; mt++)
                #pragma unroll
                for (int nt = 0; nt < 2; nt++)
                    MMA_F16(c[mt][nt][0], c[mt][nt][1], c[mt][nt][2], c[mt][nt][3],
                            a[mt][0], a[mt][1], a[mt][2], a[mt][3],
                            bf[nt][0], bf[nt][1]);
        }

        // E = exp(0.125*S) -> fp16 (tmp, Ps); row sums of fp16 values
        #pragma unroll
        for (int mt = 0; mt < 2; mt++) {
            int r1 = wm32 + mt * 16 + g;
            float eA = 0.0f, eB = 0.0f;
            #pragma unroll
            for (int nt = 0; nt < 2; nt++) {
                int col = wn16 + nt * 8 + 2 * j;
                float e0 = __expf(0.125f * c[mt][nt][0]);
                float e1 = __expf(0.125f * c[mt][nt][1]);
                float e2 = __expf(0.125f * c[mt][nt][2]);
                float e3 = __expf(0.125f * c[mt][nt][3]);
                __half2 h01 = __floats2half2_rn(e0, e1);
                __half2 h23 = __floats2half2_rn(e2, e3);
                size_t idx = ((size_t)bh * 1024 + n0 + r1) * 1024 + m0 + col;
                __stcs((unsigned int*)(tmp + idx),            *(uint32_t*)&h01);
                __stcs((unsigned int*)(tmp + idx + 8 * 1024), *(uint32_t*)&h23);
                *(uint32_t*)&Ps[r1][col]     = *(uint32_t*)&h01;
                *(uint32_t*)&Ps[r1 + 8][col] = *(uint32_t*)&h23;
                float2 f01 = __half22float2(h01);
                float2 f23 = __half22float2(h23);
                eA += f01.x + f01.y;
                eB += f23.x + f23.y;
            }
            eA += __shfl_xor_sync(0xffffffffu, eA, 1);
            eA += __shfl_xor_sync(0xffffffffu, eA, 2);
            eB += __shfl_xor_sync(0xffffffffu, eB, 1);
            eB += __shfl_xor_sync(0xffffffffu, eB, 2);
            if (j == 0) {
                sums[wn16 >> 4][r1]     += eA;
                sums[wn16 >> 4][r1 + 8] += eB;
            }
        }
        __syncthreads();

        // PV-mma: A = Ps (LDS.32 pairs), B = Vs (ldmatrix.trans)
        #pragma unroll
        for (int kk = 0; kk < 64; kk += 16) {
            uint32_t a[2][4], bf[2][2];
            #pragma unroll
            for (int mt = 0; mt < 2; mt++) {
                const __half* p0 = &Ps[wm32 + mt * 16 + g][kk + 2 * j];
                a[mt][0] = *(const uint32_t*)p0;
                a[mt][1] = *(const uint32_t*)(p0 + 8 * 72);
                a[mt][2] = *(const uint32_t*)(p0 + 8);
                a[mt][3] = *(const uint32_t*)(p0 + 8 * 72 + 8);
            }
            LDSM_X4_T(bf[0][0], bf[0][1], bf[1][0], bf[1][1],
                      vFrag + kk * 144);
            #pragma unroll
            for (int mt = 0; mt < 2; mt++)
                #pragma unroll
                for (int nt = 0; nt < 2; nt++)
                    MMA_F16(o[mt][nt][0], o[mt][nt][1], o[mt][nt][2], o[mt][nt][3],
                            a[mt][0], a[mt][1], a[mt][2], a[mt][3],
                            bf[nt][0], bf[nt][1]);
        }
    }

    __syncthreads();
    if (tid < 64) {
        float tot = sums[0][tid] + sums[1][tid] + sums[2][tid] + sums[3][tid];
        float r = 1.0f / tot;
        sums[0][tid] = r;
        rowrl[(size_t)bh * 1024 + n0 + tid] = r;
    }
    __syncthreads();

    #pragma unroll
    for (int mt = 0; mt < 2; mt++) {
        int r1 = wm32 + mt * 16 + g;
        float rlA = sums[0][r1], rlB = sums[0][r1 + 8];
        #pragma unroll
        for (int nt = 0; nt < 2; nt++) {
            int col = wn16 + nt * 8 + 2 * j;
            __half* base = attouth + ((size_t)(b * 1024 + n0 + r1) * 1024) + h * 64 + col;
            __half2 h01 = __floats2half2_rn(o[mt][nt][0] * rlA, o[mt][nt][1] * rlA);
            __half2 h23 = __floats2half2_rn(o[mt][nt][2] * rlB, o[mt][nt][3] * rlB);
            *(uint32_t*)base              = *(uint32_t*)&h01;
            *(uint32_t*)(base + 8 * 1024) = *(uint32_t*)&h23;
        }
    }
}

// ---------------------------------------------------------------------------
// Normalize + transpose: out(b,n,m,h) = E_fp16(b,h,n,m) * rl(b,h,n).
// ---------------------------------------------------------------------------
__global__ void attn_tr(const __half* __restrict__ tmp, const float* __restrict__ rowrl,
                        float* __restrict__ outAttn)
{
    int b = blockIdx.y;
    int n = blockIdx.x;
    __shared__ float T[16][257];
    __shared__ float rl_s[16];
    int tid = threadIdx.x;
    if (tid < 16) rl_s[tid] = rowrl[(size_t)(b * 16 + tid) * 1024 + n];
    __syncthreads();

    for (int m0 = 0; m0 < 1024; m0 += 256) {
        for (int i = tid; i < 512; i += 256) {
            int hh = i & 15;
            int mm = (i >> 4) * 8;
            uint4 raw = __ldcs((const uint4*)
                (tmp + ((size_t)(b * 16 + hh) * 1024 + n) * 1024 + m0 + mm));
            float rl = rl_s[hh];
            __half2 v0 = *(__half2*)&raw.x;
            __half2 v1 = *(__half2*)&raw.y;
            __half2 v2 = *(__half2*)&raw.z;
            __half2 v3 = *(__half2*)&raw.w;
            float2 f0 = __half22float2(v0);
            float2 f1 = __half22float2(v1);
            float2 f2 = __half22float2(v2);
            float2 f3 = __half22float2(v3);
            float* tr = &T[hh][mm];
            tr[0] = f0.x * rl; tr[1] = f0.y * rl;
            tr[2] = f1.x * rl; tr[3] = f1.y * rl;
            tr[4] = f2.x * rl; tr[5] = f2.y * rl;
            tr[6] = f3.x * rl; tr[7] = f3.y * rl;
        }
        __syncthreads();
        float* dst = outAttn + ((size_t)(b * 1024 + n) * 1024 + m0 + tid) * 16;
        #pragma unroll
        for (int k = 0; k < 16; k += 4) {
            __stcs((float4*)(dst + k),
                   make_float4(T[k][tid], T[k + 1][tid], T[k + 2][tid], T[k + 3][tid]));
        }
        __syncthreads();
    }
}

// ---------------------------------------------------------------------------
// Row softmax over contiguous 1024 (combine weights), fp16 out.
// ---------------------------------------------------------------------------
__global__ void row_softmax(const float* __restrict__ in, __half* __restrict__ outp)
{
    size_t row = blockIdx.x;
    const float4* L = (const float4*)(in + row * 1024);
    int t = threadIdx.x;
    float4 v = L[t];
    float mx = fmaxf(fmaxf(v.x, v.y), fmaxf(v.z, v.w));
    __shared__ float smA[8], smB[8];
    #pragma unroll
    for (int off = 16; off; off >>= 1) mx = fmaxf(mx, __shfl_xor_sync(0xffffffffu, mx, off));
    if ((t & 31) == 0) smA[t >> 5] = mx;
    __syncthreads();
    mx = smA[0];
    #pragma unroll
    for (int w = 1; w < 8; w++) mx = fmaxf(mx, smA[w]);
    float e0 = __expf(v.x - mx), e1 = __expf(v.y - mx);
    float e2 = __expf(v.z - mx), e3 = __expf(v.w - mx);
    float s = e0 + e1 + e2 + e3;
    #pragma unroll
    for (int off = 16; off; off >>= 1) s += __shfl_xor_sync(0xffffffffu, s, off);
    if ((t & 31) == 0) smB[t >> 5] = s;
    __syncthreads();
    s = 0.0f;
    #pragma unroll
    for (int w = 0; w < 8; w++) s += smB[w];
    float r = 1.0f / s;
    __half2 h01 = __floats2half2_rn(e0 * r, e1 * r);
    __half2 h23 = __floats2half2_rn(e2 * r, e3 * r);
    uint2 o;
    o.x = *(uint32_t*)&h01;
    o.y = *(uint32_t*)&h23;
    ((uint2*)(outp + row * 1024))[t] = o;
}

// ---------------------------------------------------------------------------
// Dispatch softmax over token axis n, written TRANSPOSED, fp16 out.
// ---------------------------------------------------------------------------
__global__ void disp_softmax(const float* __restrict__ logits, __half* __restrict__ dispT)
{
    int b = blockIdx.y;
    int c0 = blockIdx.x * 64;
    const float* L = logits + (size_t)b * 1048576;
    __half* O = dispT + (size_t)b * 1048576;
    int tid = threadIdx.x;
    int tx = tid & 63, ty = tid >> 6;   // 4 x 64
    int col = c0 + tx;

    __shared__ float red[4][64];
    float mx = -1e30f;
    for (int n = ty; n < 1024; n += 4) mx = fmaxf(mx, L[(size_t)n * 1024 + col]);
    red[ty][tx] = mx;
    __syncthreads();
    mx = fmaxf(fmaxf(red[0][tx], red[1][tx]), fmaxf(red[2][tx], red[3][tx]));
    __syncthreads();
    float s = 0.0f;
    for (int n = ty; n < 1024; n += 4) s += __expf(L[(size_t)n * 1024 + col] - mx);
    red[ty][tx] = s;
    __syncthreads();
    s = red[0][tx] + red[1][tx] + red[2][tx] + red[3][tx];
    float rinv = 1.0f / s;
    __syncthreads();

    __shared__ float T[64][65];
    for (int n0 = 0; n0 < 1024; n0 += 64) {
        for (int n = ty; n < 64; n += 4)
            T[tx][n] = __expf(L[(size_t)(n0 + n) * 1024 + col] - mx) * rinv;
        __syncthreads();
        int cl = tid >> 2;
        int nl = (tid & 3) * 16;
        __half* dst = O + (size_t)(c0 + cl) * 1024 + n0 + nl;
        #pragma unroll
        for (int k = 0; k < 16; k += 4) {
            __half2 h01 = __floats2half2_rn(T[cl][nl + k],     T[cl][nl + k + 1]);
            __half2 h23 = __floats2half2_rn(T[cl][nl + k + 2], T[cl][nl + k + 3]);
            uint2 o;
            o.x = *(uint32_t*)&h01;
            o.y = *(uint32_t*)&h23;
            *(uint2*)(dst + k) = o;
        }
        __syncthreads();
    }
}

// ---------------------------------------------------------------------------
// Fused residual + LayerNorm: out = LN(a + coefb * bsrc) * g + beta.
// If outH != null: values RNE-rounded to fp16, written to BOTH outputs.
// ---------------------------------------------------------------------------
__global__ void ln_res(const float* __restrict__ a, const float* __restrict__ bsrc,
                       float coefb, const float* __restrict__ g,
                       const float* __restrict__ beta, float* __restrict__ outp,
                       __half* __restrict__ outH)
{
    size_t row = blockIdx.x;
    int t = threadIdx.x;
    float4 av = ((const float4*)(a + row * 1024))[t];
    float4 bv = ((const float4*)(bsrc + row * 1024))[t];
    float x0 = av.x + coefb * bv.x;
    float x1 = av.y + coefb * bv.y;
    float x2 = av.z + coefb * bv.z;
    float x3 = av.w + coefb * bv.w;
    float s = x0 + x1 + x2 + x3;
    float q = x0 * x0 + x1 * x1 + x2 * x2 + x3 * x3;
    __shared__ float smA[8], smB[8];
    #pragma unroll
    for (int off = 16; off; off >>= 1) {
        s += __shfl_xor_sync(0xffffffffu, s, off);
        q += __shfl_xor_sync(0xffffffffu, q, off);
    }
    if ((t & 31) == 0) { smA[t >> 5] = s; smB[t >> 5] = q; }
    __syncthreads();
    s = 0.0f; q = 0.0f;
    #pragma unroll
    for (int w = 0; w < 8; w++) { s += smA[w]; q += smB[w]; }
    float mu = s * (1.0f / 1024.0f);
    float var = q * (1.0f / 1024.0f) - mu * mu;
    float rs = rsqrtf(var + 1e-5f);
    float4 gv = ((const float4*)g)[t];
    float4 btv = ((const float4*)beta)[t];
    float4 out4;
    out4.x = (x0 - mu) * rs * gv.x + btv.x;
    out4.y = (x1 - mu) * rs * gv.y + btv.y;
    out4.z = (x2 - mu) * rs * gv.z + btv.z;
    out4.w = (x3 - mu) * rs * gv.w + btv.w;
    if (outH) {
        __half2 h01 = __floats2half2_rn(out4.x, out4.y);
        __half2 h23 = __floats2half2_rn(out4.z, out4.w);
        uint2 o;
        o.x = *(uint32_t*)&h01;
        o.y = *(uint32_t*)&h23;
        ((uint2*)(outH + row * 1024))[t] = o;
        float2 f01 = __half22float2(h01);
        float2 f23 = __half22float2(h23);
        out4.x = f01.x; out4.y = f01.y; out4.z = f23.x; out4.w = f23.y;
    }
    ((float4*)(outp + row * 1024))[t] = out4;
}

// ---------------------------------------------------------------------------
// Launcher. attn_tr on a side stream overlapping proj->LN->MoE (joined
// before final LN). Stream/events created once.
// ---------------------------------------------------------------------------
static cudaStream_t g_side = nullptr;
static cudaEvent_t  g_evA  = nullptr;
static cudaEvent_t  g_evB  = nullptr;

extern "C" void kernel_launch(void* const* d_in, const int* in_sizes, int n_in,
                              void* d_out, int out_size)
{
    const float* x   = (const float*)d_in[0];
    const float* Wq  = (const float*)d_in[1];
    const float* bq  = (const float*)d_in[2];
    const float* Wkv = (const float*)d_in[3];
    const float* bkv = (const float*)d_in[4];
    const float* Wp  = (const float*)d_in[5];
    const float* bp  = (const float*)d_in[6];
    const float* g1  = (const float*)d_in[7];
    const float* b1  = (const float*)d_in[8];
    const float* phi = (const float*)d_in[9];
    const float* We1 = (const float*)d_in[10];
    const float* be1 = (const float*)d_in[11];
    const float* We2 = (const float*)d_in[12];
    const float* be2 = (const float*)d_in[13];
    const float* g2  = (const float*)d_in[14];
    const float* b2  = (const float*)d_in[15];

    if (!g_side) {
        cudaStreamCreateWithFlags(&g_side, cudaStreamNonBlocking);
        cudaEventCreateWithFlags(&g_evA, cudaEventDisableTiming);
        cudaEventCreateWithFlags(&g_evB, cudaEventDisableTiming);
    }

    float* arena = nullptr;
    cudaGetSymbolAddress((void**)&arena, g_arena);

    __half* tmp     = (__half*)(arena + OFF_TMP);
    float*  proj    = arena + OFF_PROJ;
    float*  x1      = arena + OFF_X1;
    float*  logits  = arena + OFF_LOGITS;
    float*  moeout  = arena + OFF_MOE;
    float*  rl      = arena + OFF_RL;
    __half* xh      = (__half*)(arena + OFF_XH);
    __half* Wqkvh   = (__half*)(arena + OFF_WQKVH);
    __half* Wph     = (__half*)(arena + OFF_WPH);
    __half* phih    = (__half*)(arena + OFF_PHIH);
    __half* We1h    = (__half*)(arena + OFF_WE1H);
    __half* We2h    = (__half*)(arena + OFF_WE2H);
    __half* qkvh    = (__half*)(arena + OFF_QKVH);
    __half* attouth = (__half*)(arena + OFF_ATTOUTH);
    __half* x1h     = (__half*)(arena + OFF_X1H);
    __half* dispTh  = (__half*)(arena + OFF_DISPTH);
    __half* combh   = (__half*)(arena + OFF_COMBH);
    __half* slotsh  = (__half*)(arena + OFF_SLOTSH);
    __half* hh      = (__half*)(arena + OFF_HH);
    __half* ymoeh   = (__half*)(arena + OFF_YMOEH);
    float*  bqkv    = arena + OFF_BQKV;

    float* out = (float*)d_out;
    float* outAttn = out + 4194304;

    dim3 T(256);

    // prep: RNE-round all GEMM inputs to fp16 + concat W_qkv/bias, one launch
    round_all<<<25603, T>>>(x, Wq, Wkv, Wp, phi, We1, We2, bq, bkv,
                            xh, Wqkvh, Wph, phih, We1h, We2h, bqkv);

    // qkv = x @ Wqkv + bqkv    (4096x3072x1024) -> fp16 (one fused GEMM)
    hgemm<<<dim3(24, 32, 1), T>>>(xh, Wqkvh, bqkv, nullptr, qkvh, 4096, 3072, 1024,
                                  0, 0, 0, 0, 1, 1);

    // fused attention
    att_fused<<<dim3(16, 64), T>>>(qkvh, tmp, rl, attouth);

    // fork: attn_tr on side stream (depends only on att_fused outputs)
    cudaEventRecord(g_evA, 0);
    cudaStreamWaitEvent(g_side, g_evA, 0);
    attn_tr<<<dim3(1024, 4), T, 0, g_side>>>(tmp, rl, outAttn);
    cudaEventRecord(g_evB, g_side);

    // out-proj (f32) + residual LN (x1 f32 + fp16)   [main stream]
    hgemm<<<dim3(8, 32, 1), T>>>(attouth, Wph, bp, proj, nullptr, 4096, 1024, 1024,
                                 0, 0, 0, 0, 1, 1);
    ln_res<<<4096, T>>>(proj, x, 1.0f, g1, b1, x1, x1h);

    // soft-MoE
    hgemm<<<dim3(8, 32, 1), T>>>(x1h, phih, nullptr, logits, nullptr, 4096, 1024, 1024,
                                 0, 0, 0, 0, 1, 0);
    row_softmax<<<4096, T>>>(logits, combh);
    disp_softmax<<<dim3(16, 4), T>>>(logits, dispTh);

    // slots[b] = dispT[b] @ x1[b] -> fp16
    hgemm<<<dim3(8, 8, 4), T>>>(dispTh, x1h, nullptr, nullptr, slotsh, 1024, 1024, 1024,
                                1048576, 1048576, 0, 1048576, 0, 0);
    // h = gelu(slots @ We1[e] + be1[e]) -> fp16
    hgemm<<<dim3(32, 4, 8), T>>>(slotsh, We1h, be1, nullptr, hh, 512, 4096, 1024,
                                 524288, 4194304, 4096, 2097152, 2, 2);
    // y = h @ We2[e] + be2[e] -> fp16
    hgemm<<<dim3(8, 4, 8), T>>>(hh, We2h, be2, nullptr, ymoeh, 512, 1024, 4096,
                                2097152, 4194304, 1024, 524288, 2, 1);
    // moe_out[b] = comb[b] @ ymoe[b] -> f32
    hgemm<<<dim3(8, 8, 4), T>>>(combh, ymoeh, nullptr, moeout, nullptr, 1024, 1024, 1024,
                                1048576, 1048576, 0, 1048576, 0, 0);

    // join side stream, then final LN
    cudaStreamWaitEvent(0, g_evB, 0);
    ln_res<<<4096, T>>>(moeout, x1, 2.0f, g2, b2, out, nullptr);
}